// round 13
// baseline (speedup 1.0000x reference)
#include <cuda_runtime.h>
#include <cuda_bf16.h>

typedef unsigned long long u64;
typedef unsigned int u32;

// ---------------- mma.sync bf16 helpers ----------------
__device__ __forceinline__ u32 prmt(u32 a, u32 b, u32 s) {
    u32 d; asm("prmt.b32 %0, %1, %2, %3;" : "=r"(d) : "r"(a), "r"(b), "r"(s));
    return d;
}
__device__ __forceinline__ void mma_bf16(float4& c, u32 a0, u32 a1, u32 a2, u32 a3,
                                         u32 b0, u32 b1) {
    asm("mma.sync.aligned.m16n8k16.row.col.f32.bf16.bf16.f32 "
        "{%0,%1,%2,%3}, {%4,%5,%6,%7}, {%8,%9}, {%0,%1,%2,%3};"
        : "+f"(c.x), "+f"(c.y), "+f"(c.z), "+f"(c.w)
        : "r"(a0), "r"(a1), "r"(a2), "r"(a3), "r"(b0), "r"(b1));
}
// fp32 -> {bf16 hi (low16), bf16 lo (high16)} packed u32
__device__ __forceinline__ u32 pack_hl(float a) {
    __nv_bfloat16 hb = __float2bfloat16_rn(a);
    float r = a - __bfloat162float(hb);
    __nv_bfloat16 lb = __float2bfloat16_rn(r);
    return (u32)__bfloat16_as_ushort(hb) | ((u32)__bfloat16_as_ushort(lb) << 16);
}
__device__ __forceinline__ void split_pair(float2 w, u32& hiw, u32& low) {
    __nv_bfloat16 h0 = __float2bfloat16_rn(w.x);
    __nv_bfloat16 h1 = __float2bfloat16_rn(w.y);
    float r0 = w.x - __bfloat162float(h0);
    float r1 = w.y - __bfloat162float(h1);
    __nv_bfloat16 l0 = __float2bfloat16_rn(r0);
    __nv_bfloat16 l1 = __float2bfloat16_rn(r1);
    hiw = (u32)__bfloat16_as_ushort(h0) | ((u32)__bfloat16_as_ushort(h1) << 16);
    low = (u32)__bfloat16_as_ushort(l0) | ((u32)__bfloat16_as_ushort(l1) << 16);
}
__device__ __forceinline__ u32 smem_u32(const void* p) {
    u32 a; asm("{ .reg .u64 t; cvta.to.shared.u64 t, %1; cvt.u32.u64 %0, t; }" : "=r"(a) : "l"(p));
    return a;
}
__device__ __forceinline__ void cp16(u32 dst, const void* src) {
    asm volatile("cp.async.cg.shared.global [%0], [%1], 16;" :: "r"(dst), "l"(src));
}
#define CP_COMMIT() asm volatile("cp.async.commit_group;" ::: "memory")
#define CP_WAIT0()  asm volatile("cp.async.wait_group 0;" ::: "memory")

// ---------------- problem constants ----------------
#define NB   8
#define MCO  9
#define AA   42
#define XW   1152
#define THREADS 512

// ---------------- prepacked weights (filled by prep_kernel) ----------------
__device__ u32 g_gw_pack[8 * 4096];   // grid_w: [8 kc][hi:2048 | lo:2048]
__device__ u32 g_w1_pack[8 * 6144];   // w1: [8 kc][hi:3072 | lo:3072], n=deg*128+h
__device__ u32 g_w2_pack[8 * 6144];

// ---------------- shared memory layout (floats) ----------------
#define S_G    0                    // 336*128 (g/gg/out; rows 80+ alias W staging for GEMM1/3)
#define S_B1   43008                // 72*128 (h1/h2); GEMM2 B staging aliases (8192 u32)
#define S_TG   56320
#define S_FG   (S_TG + 378)
#define S_GB   (S_FG + 378)
#define S_BB1  (S_GB + 256)
#define S_BB2  (S_BB1 + 128)
#define S_NW   (S_BB2 + 128)
#define S_RED  (S_NW + 384)
#define SMEM_FLOATS (S_RED + 16)

// ---------------- prep kernel: convert weights once ----------------
extern "C" __global__ void prep_kernel(const float* __restrict__ gw,
                                       const float* __restrict__ w1,
                                       const float* __restrict__ w2)
{
    const int t = blockIdx.x * blockDim.x + threadIdx.x;
    const int stride = gridDim.x * blockDim.x;
    for (int p = t; p < 16384; p += stride) {
        int n = p >> 6, kc = (p >> 3) & 7, j = p & 7;
        float2 w = *(const float2*)(gw + n * 128 + kc * 16 + 2 * j);
        u32 hiw, low; split_pair(w, hiw, low);
        int pos = 2 * (j & 3) + (j >> 2);
        g_gw_pack[kc * 4096 + n * 8 + pos] = hiw;
        g_gw_pack[kc * 4096 + 2048 + n * 8 + pos] = low;
    }
    for (int p = t; p < 24576; p += stride) {
        int n = p >> 6, kc = (p >> 3) & 7, j = p & 7;
        int pos = 2 * (j & 3) + (j >> 2);
        {
            float2 w = *(const float2*)(w1 + n * 128 + kc * 16 + 2 * j);
            u32 hiw, low; split_pair(w, hiw, low);
            g_w1_pack[kc * 6144 + n * 8 + pos] = hiw;
            g_w1_pack[kc * 6144 + 3072 + n * 8 + pos] = low;
        }
        {
            float2 w = *(const float2*)(w2 + n * 128 + kc * 16 + 2 * j);
            u32 hiw, low; split_pair(w, hiw, low);
            g_w2_pack[kc * 6144 + n * 8 + pos] = hiw;
            g_w2_pack[kc * 6144 + 3072 + n * 8 + pos] = low;
        }
    }
}

// ---------------- GEMM1/GEMM3: per-degree 72x128x128 via mma.sync ----------------
// Apk: packed A (72 rows x 128 u32). wpk: prepacked weights. O: fp32 72x128.
// wbuf: smem staging 2*6144 u32 (cp.async double-buffered).
__device__ __forceinline__ void gemm_degree_mma(const u32* __restrict__ Apk,
                                                const u32* __restrict__ wpk,
                                                float* __restrict__ O,
                                                const float* __restrict__ bias0,
                                                u32* __restrict__ wbuf)
{
    const int tid  = threadIdx.x;
    const int lane = tid & 31;
    const int wrp  = tid >> 5;
    const u32 wbuf_addr = smem_u32(wbuf);

    // prologue: issue chunk 0 into buffer 0
    for (int p = tid; p < 1536; p += THREADS)
        cp16(wbuf_addr + p * 16, ((const uint4*)wpk) + p);
    CP_COMMIT();

    const int tile = (wrp < 12) ? (wrp >> 1) : 0;
    const int nh   = wrp & 1;
    int trow, tval, tdeg;
    if (tile == 0)      { trow = 0;                 tval = 8;                  tdeg = 0; }
    else if (tile <= 2) { trow = 8 + 16 * (tile - 1);  tval = (tile == 1) ? 16 : 8;  tdeg = 1; }
    else                { trow = 32 + 16 * (tile - 3); tval = (tile == 5) ? 8 : 16;  tdeg = 2; }

    float4 c[8];
#pragma unroll
    for (int i = 0; i < 8; i++) c[i] = make_float4(0.f, 0.f, 0.f, 0.f);

    const int r0 = trow + (lane >> 2);
    const u32* Ar = Apk + r0 * 128 + (lane & 3) * 2;
    const int bbase = (tdeg * 128 + nh * 64) * 8 + 2 * (lane & 3);

    for (int kc = 0; kc < 8; kc++) {
        CP_WAIT0();
        __syncthreads();
        if (kc < 7) {
            const uint4* src = (const uint4*)(wpk + (kc + 1) * 6144);
            const u32 dstb = wbuf_addr + ((kc + 1) & 1) * 24576;
            for (int p = tid; p < 1536; p += THREADS)
                cp16(dstb + p * 16, src + p);
            CP_COMMIT();
        }
        if (wrp < 12) {
            const u32* a = Ar + kc * 16;
            u64 L0 = *(const u64*)(a);
            u64 L1 = *(const u64*)(a + 8 * 128);
            u64 L2 = *(const u64*)(a + 8);
            u64 L3 = *(const u64*)(a + 8 * 128 + 8);
            u32 ah0, ah1, ah2, ah3, al0, al1, al2, al3;
            { u32 p0 = (u32)L0, p1 = (u32)(L0 >> 32); ah0 = prmt(p0, p1, 0x5410); al0 = prmt(p0, p1, 0x7632); }
            { u32 p0 = (u32)L1, p1 = (u32)(L1 >> 32); ah1 = prmt(p0, p1, 0x5410); al1 = prmt(p0, p1, 0x7632); }
            { u32 p0 = (u32)L2, p1 = (u32)(L2 >> 32); ah2 = prmt(p0, p1, 0x5410); al2 = prmt(p0, p1, 0x7632); }
            { u32 p0 = (u32)L3, p1 = (u32)(L3 >> 32); ah3 = prmt(p0, p1, 0x5410); al3 = prmt(p0, p1, 0x7632); }

            const u32* bu = wbuf + (kc & 1) * 6144 + bbase;
#pragma unroll
            for (int i = 0; i < 8; i++) {
                const int noff = (i * 8 + (lane >> 2)) * 8;
                u64 H = *(const u64*)(bu + noff);
                u64 L = *(const u64*)(bu + 3072 + noff);
                u32 bh0 = (u32)H, bh1 = (u32)(H >> 32);
                u32 bl0 = (u32)L, bl1 = (u32)(L >> 32);
                mma_bf16(c[i], ah0, ah1, ah2, ah3, bh0, bh1);
                mma_bf16(c[i], ah0, ah1, ah2, ah3, bl0, bl1);
                mma_bf16(c[i], al0, al1, al2, al3, bh0, bh1);
            }
        }
    }

    if (wrp < 12) {
        const bool wr0 = (lane >> 2) < tval;
        const bool wr1 = (lane >> 2) + 8 < tval;
#pragma unroll
        for (int i = 0; i < 8; i++) {
            const int col = nh * 64 + i * 8 + 2 * (lane & 3);
            float2 o0 = make_float2(c[i].x, c[i].y);
            float2 o1 = make_float2(c[i].z, c[i].w);
            if (tile == 0) {
                float b0 = bias0[col], b1 = bias0[col + 1];
                o0.x += b0; o0.y += b1;
                o1.x += b0; o1.y += b1;
            }
            if (wr0) *(float2*)(O + r0 * 128 + col) = o0;
            if (wr1) *(float2*)(O + (r0 + 8) * 128 + col) = o1;
        }
    }
}

extern "C" __global__ void __launch_bounds__(THREADS, 1)
eqffn_kernel(const float* __restrict__ x,
             const float* __restrict__ nwg,
             const float* __restrict__ b1g,
             const float* __restrict__ gbg,
             const float* __restrict__ b2g,
             const float* __restrict__ tgg,
             const float* __restrict__ fgg,
             float* __restrict__ y,
             int N)
{
    extern __shared__ __align__(16) float sm[];
    float* s_g   = sm + S_G;
    float* s_h1  = sm + S_B1;
    float* s_tg  = sm + S_TG;
    float* s_fg  = sm + S_FG;
    float* s_gb  = sm + S_GB;
    float* s_bb1 = sm + S_BB1;
    float* s_bb2 = sm + S_BB2;
    float* s_nw  = sm + S_NW;
    float* s_red = sm + S_RED;

    const int tid  = threadIdx.x;
    const int lane = tid & 31;
    const int wrp  = tid >> 5;
    const int nodl = wrp >> 1;
    const int half = wrp & 1;

    for (int i = tid; i < 378; i += THREADS) s_tg[i] = tgg[i];
    for (int i = tid; i < 378; i += THREADS) s_fg[i] = fgg[i];
    if (tid < 256) s_gb[tid] = gbg[tid];
    if (tid < 128) { s_bb1[tid] = b1g[tid]; s_bb2[tid] = b2g[tid]; }
    if (tid < 384) s_nw[tid] = nwg[tid];

    const int node = blockIdx.x * NB + nodl;
    const bool valid = node < N;

    // ---------- Phase 0: load x, sumsq, RMS-norm, write PACKED A for GEMM1 ----------
    float v[18];
    float ss = 0.f;
    if (valid) {
        const float* xr = x + (size_t)node * XW + half * 576;
#pragma unroll
        for (int k = 0; k < 18; k++) { v[k] = xr[lane + 32 * k]; ss += v[k] * v[k]; }
    } else {
#pragma unroll
        for (int k = 0; k < 18; k++) v[k] = 0.f;
    }
#pragma unroll
    for (int o = 16; o; o >>= 1) ss += __shfl_xor_sync(0xffffffffu, ss, o);
    if (lane == 0) s_red[wrp] = ss;
    __syncthreads();
    const float sst = s_red[nodl * 2] + s_red[nodl * 2 + 1];
    const float rinv = rsqrtf(sst * (1.0f / 1152.0f) + 1e-6f);

#pragma unroll
    for (int k = 0; k < 18; k++) {
        int j = half * 576 + lane + 32 * k;
        int l, coeff, c;
        if (j < 128)      { l = 0; coeff = 0; c = j; }
        else if (j < 512) { l = 1; int q = j - 128; c = q / 3; coeff = 1 + (q - 3 * c); }
        else              { l = 2; int q = j - 512; c = q / 5; coeff = 4 + (q - 5 * c); }
        ((u32*)s_g)[(coeff * NB + nodl) * 128 + c] = pack_hl(v[k] * rinv * s_nw[l * 128 + c]);
    }
    __syncthreads();

    // ---------- Phase 1: GEMM1 via mma (A already packed) ----------
    gemm_degree_mma((const u32*)s_g, g_w1_pack, s_h1, s_bb1, (u32*)(s_g + 10240));
    __syncthreads();

    // ---------- Phase 2: to_grid -> write PACKED A for GEMM2 ----------
    {
        float4 h1r[MCO];
#pragma unroll
        for (int m = 0; m < MCO; m++)
            h1r[m] = ((const float4*)s_h1)[(m * NB + nodl) * 32 + lane];
        const int a0 = half * 21;
        for (int a = a0; a < a0 + 21; a++) {
            float4 acc = make_float4(0.f, 0.f, 0.f, 0.f);
#pragma unroll
            for (int m = 0; m < MCO; m++) {
                float t = s_tg[a * MCO + m];
                acc.x += t * h1r[m].x; acc.y += t * h1r[m].y;
                acc.z += t * h1r[m].z; acc.w += t * h1r[m].w;
            }
            uint4 pk;
            pk.x = pack_hl(acc.x); pk.y = pack_hl(acc.y);
            pk.z = pack_hl(acc.z); pk.w = pack_hl(acc.w);
            ((uint4*)s_g)[(nodl * AA + a) * 32 + lane] = pk;
        }
    }
    __syncthreads();

    // ---------- Phase 3+4: GEMM2 (336x256x128) via mma + SwiGLU ----------
    {
        u32* sgu  = (u32*)s_g;
        u32* bbuf = (u32*)s_h1;
        const u32 bbuf_addr = smem_u32(bbuf);

        // prologue: issue chunk 0
        for (int p = tid; p < 1024; p += THREADS)
            cp16(bbuf_addr + p * 16, ((const uint4*)g_gw_pack) + p);
        CP_COMMIT();

        const int rt = (wrp < 14) ? (wrp % 7) : 0;
        const int ch = (wrp < 14) ? (wrp / 7) : 0;
        const int rr = rt * 16 + (lane >> 2);
        const int ks = (lane & 3) * 2;

        for (int b = 0; b < 3; b++) {
            const int rbase = b * 112;
            float4 c[16];
#pragma unroll
            for (int i = 0; i < 16; i++) c[i] = make_float4(0.f, 0.f, 0.f, 0.f);

            for (int kc = 0; kc < 8; kc++) {
                CP_WAIT0();
                __syncthreads();
                const int g = b * 8 + kc;
                if (g < 23) {
                    const int nkc = (kc + 1) & 7;
                    const uint4* src = (const uint4*)(g_gw_pack + nkc * 4096);
                    const u32 dstb = bbuf_addr + ((g + 1) & 1) * 16384;
                    for (int p = tid; p < 1024; p += THREADS)
                        cp16(dstb + p * 16, src + p);
                    CP_COMMIT();
                }

                if (wrp < 14) {
                    const u32* Ar = sgu + (rbase + rr) * 128 + kc * 16 + ks;
                    u64 L0 = *(const u64*)(Ar);
                    u64 L1 = *(const u64*)(Ar + 8 * 128);
                    u64 L2 = *(const u64*)(Ar + 8);
                    u64 L3 = *(const u64*)(Ar + 8 * 128 + 8);
                    u32 ah0, ah1, ah2, ah3, al0, al1, al2, al3;
                    { u32 p0 = (u32)L0, p1 = (u32)(L0 >> 32); ah0 = prmt(p0, p1, 0x5410); al0 = prmt(p0, p1, 0x7632); }
                    { u32 p0 = (u32)L1, p1 = (u32)(L1 >> 32); ah1 = prmt(p0, p1, 0x5410); al1 = prmt(p0, p1, 0x7632); }
                    { u32 p0 = (u32)L2, p1 = (u32)(L2 >> 32); ah2 = prmt(p0, p1, 0x5410); al2 = prmt(p0, p1, 0x7632); }
                    { u32 p0 = (u32)L3, p1 = (u32)(L3 >> 32); ah3 = prmt(p0, p1, 0x5410); al3 = prmt(p0, p1, 0x7632); }

                    const u32* bu = bbuf + (g & 1) * 4096;
                    const int jsel2 = 2 * (lane & 3);
#pragma unroll
                    for (int i = 0; i < 16; i++) {
                        const int nt = (i < 8) ? (ch * 8 + i) : (16 + ch * 8 + (i - 8));
                        const int n  = nt * 8 + (lane >> 2);
                        u64 H = *(const u64*)(bu + n * 8 + jsel2);
                        u64 L = *(const u64*)(bu + 2048 + n * 8 + jsel2);
                        u32 bh0 = (u32)H, bh1 = (u32)(H >> 32);
                        u32 bl0 = (u32)L, bl1 = (u32)(L >> 32);
                        mma_bf16(c[i], ah0, ah1, ah2, ah3, bh0, bh1);
                        mma_bf16(c[i], ah0, ah1, ah2, ah3, bl0, bl1);
                        mma_bf16(c[i], al0, al1, al2, al3, bh0, bh1);
                    }
                }
            }
            __syncthreads();   // all MMA reads of this block's A rows done before epilogue writes

            if (wrp < 14) {
                const int r0 = rbase + rr;
#pragma unroll
                for (int i = 0; i < 8; i++) {
                    const int h0 = ch * 64 + i * 8 + (lane & 3) * 2;
                    const float bz0 = s_gb[h0], bz1 = s_gb[h0 + 1];
                    const float bg0 = s_gb[128 + h0], bg1 = s_gb[128 + h0 + 1];
                    float4 z4 = c[i], g4 = c[i + 8];
                    float z0 = z4.x + bz0, z1 = z4.y + bz1;
                    float z2 = z4.z + bz0, z3 = z4.w + bz1;
                    float g0 = g4.x + bg0, g1 = g4.y + bg1;
                    float g2 = g4.z + bg0, g3 = g4.w + bg1;
                    float2 o01, o23;
                    o01.x = z0 * (1.f / (1.f + __expf(-z0))) * g0;
                    o01.y = z1 * (1.f / (1.f + __expf(-z1))) * g1;
                    o23.x = z2 * (1.f / (1.f + __expf(-z2))) * g2;
                    o23.y = z3 * (1.f / (1.f + __expf(-z3))) * g3;
                    *(float2*)(s_g + r0 * 128 + h0) = o01;
                    *(float2*)(s_g + (r0 + 8) * 128 + h0) = o23;
                }
            }
        }
    }
    __syncthreads();

    // ---------- Phase 5: from_grid -> write PACKED A for GEMM3 ----------
    {
        const int m0   = half ? 5 : 0;
        const int mcnt = half ? 4 : 5;
        float4 acc[5];
#pragma unroll
        for (int m = 0; m < 5; m++) acc[m] = make_float4(0.f, 0.f, 0.f, 0.f);
        for (int a = 0; a < AA; a++) {
            float4 g4 = ((const float4*)s_g)[(nodl * AA + a) * 32 + lane];
#pragma unroll
            for (int m = 0; m < 5; m++) {
                if (m < mcnt) {
                    float f = s_fg[(m0 + m) * AA + a];
                    acc[m].x += f * g4.x; acc[m].y += f * g4.y;
                    acc[m].z += f * g4.z; acc[m].w += f * g4.w;
                }
            }
        }
#pragma unroll
        for (int m = 0; m < 5; m++)
            if (m < mcnt) {
                uint4 pk;
                pk.x = pack_hl(acc[m].x); pk.y = pack_hl(acc[m].y);
                pk.z = pack_hl(acc[m].z); pk.w = pack_hl(acc[m].w);
                ((uint4*)s_h1)[((m0 + m) * NB + nodl) * 32 + lane] = pk;
            }
    }
    __syncthreads();

    // ---------- Phase 6: GEMM3 via mma ----------
    gemm_degree_mma((const u32*)s_h1, g_w2_pack, s_g, s_bb2, (u32*)(s_g + 10240));
    __syncthreads();

    // ---------- Phase 7: unpack + store ----------
    if (valid) {
        float* yr = y + (size_t)node * XW;
#pragma unroll
        for (int k = 0; k < 18; k++) {
            int j = half * 576 + lane + 32 * k;
            int coeff, c;
            if (j < 128)      { coeff = 0; c = j; }
            else if (j < 512) { int q = j - 128; c = q / 3; coeff = 1 + (q - 3 * c); }
            else              { int q = j - 512; c = q / 5; coeff = 4 + (q - 5 * c); }
            yr[j] = s_g[(coeff * NB + nodl) * 128 + c];
        }
    }
}

extern "C" void kernel_launch(void* const* d_in, const int* in_sizes, int n_in,
                              void* d_out, int out_size)
{
    const float* x   = (const float*)d_in[0];
    const float* nw  = (const float*)d_in[1];
    const float* w1  = (const float*)d_in[2];
    const float* b1  = (const float*)d_in[3];
    const float* gw  = (const float*)d_in[4];
    const float* gb  = (const float*)d_in[5];
    const float* w2  = (const float*)d_in[6];
    const float* b2  = (const float*)d_in[7];
    const float* tg  = (const float*)d_in[8];
    const float* fg  = (const float*)d_in[9];
    float* y = (float*)d_out;

    const int N = in_sizes[0] / XW;

    prep_kernel<<<128, 512>>>(gw, w1, w2);

    const int smem_bytes = SMEM_FLOATS * 4;
    cudaFuncSetAttribute(eqffn_kernel, cudaFuncAttributeMaxDynamicSharedMemorySize, smem_bytes);
    const int grid = (N + NB - 1) / NB;
    eqffn_kernel<<<grid, THREADS, smem_bytes>>>(x, nw, b1, gb, b2, tg, fg, y, N);
}

// round 14
// speedup vs baseline: 1.0006x; 1.0006x over previous
#include <cuda_runtime.h>
#include <cuda_bf16.h>

typedef unsigned long long u64;
typedef unsigned int u32;

// ---------------- mma.sync bf16 helpers ----------------
__device__ __forceinline__ u32 prmt(u32 a, u32 b, u32 s) {
    u32 d; asm("prmt.b32 %0, %1, %2, %3;" : "=r"(d) : "r"(a), "r"(b), "r"(s));
    return d;
}
__device__ __forceinline__ void mma_bf16(float4& c, u32 a0, u32 a1, u32 a2, u32 a3,
                                         u32 b0, u32 b1) {
    asm("mma.sync.aligned.m16n8k16.row.col.f32.bf16.bf16.f32 "
        "{%0,%1,%2,%3}, {%4,%5,%6,%7}, {%8,%9}, {%0,%1,%2,%3};"
        : "+f"(c.x), "+f"(c.y), "+f"(c.z), "+f"(c.w)
        : "r"(a0), "r"(a1), "r"(a2), "r"(a3), "r"(b0), "r"(b1));
}
// fp32 -> {bf16 hi (low16), bf16 lo (high16)} packed u32
__device__ __forceinline__ u32 pack_hl(float a) {
    __nv_bfloat16 hb = __float2bfloat16_rn(a);
    float r = a - __bfloat162float(hb);
    __nv_bfloat16 lb = __float2bfloat16_rn(r);
    return (u32)__bfloat16_as_ushort(hb) | ((u32)__bfloat16_as_ushort(lb) << 16);
}
__device__ __forceinline__ void split_pair(float2 w, u32& hiw, u32& low) {
    __nv_bfloat16 h0 = __float2bfloat16_rn(w.x);
    __nv_bfloat16 h1 = __float2bfloat16_rn(w.y);
    float r0 = w.x - __bfloat162float(h0);
    float r1 = w.y - __bfloat162float(h1);
    __nv_bfloat16 l0 = __float2bfloat16_rn(r0);
    __nv_bfloat16 l1 = __float2bfloat16_rn(r1);
    hiw = (u32)__bfloat16_as_ushort(h0) | ((u32)__bfloat16_as_ushort(h1) << 16);
    low = (u32)__bfloat16_as_ushort(l0) | ((u32)__bfloat16_as_ushort(l1) << 16);
}
__device__ __forceinline__ u32 smem_u32(const void* p) {
    u32 a; asm("{ .reg .u64 t; cvta.to.shared.u64 t, %1; cvt.u32.u64 %0, t; }" : "=r"(a) : "l"(p));
    return a;
}
__device__ __forceinline__ void cp16(u32 dst, const void* src) {
    asm volatile("cp.async.cg.shared.global [%0], [%1], 16;" :: "r"(dst), "l"(src));
}
#define CP_COMMIT() asm volatile("cp.async.commit_group;" ::: "memory")
#define CP_WAIT0()  asm volatile("cp.async.wait_group 0;" ::: "memory")

// ---------------- problem constants ----------------
#define NB   8
#define MCO  9
#define AA   42
#define XW   1152
#define THREADS 512

// ---------------- prepacked weights (filled by prep_kernel) ----------------
__device__ u32 g_gw_pack[8 * 4096];   // grid_w: [8 kc][hi:2048 | lo:2048]
__device__ u32 g_w1_pack[8 * 6144];   // w1: [8 kc][hi:3072 | lo:3072], n=deg*128+h
__device__ u32 g_w2_pack[8 * 6144];

// ---------------- shared memory layout (floats) ----------------
#define S_G    0                    // 336*128 (g/gg/out; rows 80+ alias W staging for GEMM1/3)
#define S_B1   43008                // 72*128 (h1/h2); GEMM2 B staging aliases (8192 u32)
#define S_TG   56320
#define S_FG   (S_TG + 378)
#define S_GB   (S_FG + 378)
#define S_BB1  (S_GB + 256)
#define S_BB2  (S_BB1 + 128)
#define S_NW   (S_BB2 + 128)
#define S_RED  (S_NW + 384)
#define SMEM_FLOATS (S_RED + 16)

// ---------------- prep kernel: convert weights once ----------------
extern "C" __global__ void prep_kernel(const float* __restrict__ gw,
                                       const float* __restrict__ w1,
                                       const float* __restrict__ w2)
{
    const int t = blockIdx.x * blockDim.x + threadIdx.x;
    const int stride = gridDim.x * blockDim.x;
    for (int p = t; p < 16384; p += stride) {
        int n = p >> 6, kc = (p >> 3) & 7, j = p & 7;
        float2 w = *(const float2*)(gw + n * 128 + kc * 16 + 2 * j);
        u32 hiw, low; split_pair(w, hiw, low);
        int pos = 2 * (j & 3) + (j >> 2);
        g_gw_pack[kc * 4096 + n * 8 + pos] = hiw;
        g_gw_pack[kc * 4096 + 2048 + n * 8 + pos] = low;
    }
    for (int p = t; p < 24576; p += stride) {
        int n = p >> 6, kc = (p >> 3) & 7, j = p & 7;
        int pos = 2 * (j & 3) + (j >> 2);
        {
            float2 w = *(const float2*)(w1 + n * 128 + kc * 16 + 2 * j);
            u32 hiw, low; split_pair(w, hiw, low);
            g_w1_pack[kc * 6144 + n * 8 + pos] = hiw;
            g_w1_pack[kc * 6144 + 3072 + n * 8 + pos] = low;
        }
        {
            float2 w = *(const float2*)(w2 + n * 128 + kc * 16 + 2 * j);
            u32 hiw, low; split_pair(w, hiw, low);
            g_w2_pack[kc * 6144 + n * 8 + pos] = hiw;
            g_w2_pack[kc * 6144 + 3072 + n * 8 + pos] = low;
        }
    }
}

// ---------------- GEMM1/GEMM3: per-degree 72x128x128 via mma.sync ----------------
// Apk: packed A (72 rows x 128 u32). wpk: prepacked weights. O: fp32 72x128.
// wbuf: smem staging 2*6144 u32 (cp.async double-buffered).
__device__ __forceinline__ void gemm_degree_mma(const u32* __restrict__ Apk,
                                                const u32* __restrict__ wpk,
                                                float* __restrict__ O,
                                                const float* __restrict__ bias0,
                                                u32* __restrict__ wbuf)
{
    const int tid  = threadIdx.x;
    const int lane = tid & 31;
    const int wrp  = tid >> 5;
    const u32 wbuf_addr = smem_u32(wbuf);

    // prologue: issue chunk 0 into buffer 0
    for (int p = tid; p < 1536; p += THREADS)
        cp16(wbuf_addr + p * 16, ((const uint4*)wpk) + p);
    CP_COMMIT();

    const int tile = (wrp < 12) ? (wrp >> 1) : 0;
    const int nh   = wrp & 1;
    int trow, tval, tdeg;
    if (tile == 0)      { trow = 0;                 tval = 8;                  tdeg = 0; }
    else if (tile <= 2) { trow = 8 + 16 * (tile - 1);  tval = (tile == 1) ? 16 : 8;  tdeg = 1; }
    else                { trow = 32 + 16 * (tile - 3); tval = (tile == 5) ? 8 : 16;  tdeg = 2; }

    float4 c[8];
#pragma unroll
    for (int i = 0; i < 8; i++) c[i] = make_float4(0.f, 0.f, 0.f, 0.f);

    const int r0 = trow + (lane >> 2);
    const u32* Ar = Apk + r0 * 128 + (lane & 3) * 2;
    const int bbase = (tdeg * 128 + nh * 64) * 8 + 2 * (lane & 3);

    for (int kc = 0; kc < 8; kc++) {
        CP_WAIT0();
        __syncthreads();
        if (kc < 7) {
            const uint4* src = (const uint4*)(wpk + (kc + 1) * 6144);
            const u32 dstb = wbuf_addr + ((kc + 1) & 1) * 24576;
            for (int p = tid; p < 1536; p += THREADS)
                cp16(dstb + p * 16, src + p);
            CP_COMMIT();
        }
        if (wrp < 12) {
            const u32* a = Ar + kc * 16;
            u64 L0 = *(const u64*)(a);
            u64 L1 = *(const u64*)(a + 8 * 128);
            u64 L2 = *(const u64*)(a + 8);
            u64 L3 = *(const u64*)(a + 8 * 128 + 8);
            u32 ah0, ah1, ah2, ah3, al0, al1, al2, al3;
            { u32 p0 = (u32)L0, p1 = (u32)(L0 >> 32); ah0 = prmt(p0, p1, 0x5410); al0 = prmt(p0, p1, 0x7632); }
            { u32 p0 = (u32)L1, p1 = (u32)(L1 >> 32); ah1 = prmt(p0, p1, 0x5410); al1 = prmt(p0, p1, 0x7632); }
            { u32 p0 = (u32)L2, p1 = (u32)(L2 >> 32); ah2 = prmt(p0, p1, 0x5410); al2 = prmt(p0, p1, 0x7632); }
            { u32 p0 = (u32)L3, p1 = (u32)(L3 >> 32); ah3 = prmt(p0, p1, 0x5410); al3 = prmt(p0, p1, 0x7632); }

            const u32* bu = wbuf + (kc & 1) * 6144 + bbase;
#pragma unroll
            for (int i = 0; i < 8; i++) {
                const int noff = (i * 8 + (lane >> 2)) * 8;
                u64 H = *(const u64*)(bu + noff);
                u64 L = *(const u64*)(bu + 3072 + noff);
                u32 bh0 = (u32)H, bh1 = (u32)(H >> 32);
                u32 bl0 = (u32)L, bl1 = (u32)(L >> 32);
                mma_bf16(c[i], ah0, ah1, ah2, ah3, bh0, bh1);
                mma_bf16(c[i], ah0, ah1, ah2, ah3, bl0, bl1);
                mma_bf16(c[i], al0, al1, al2, al3, bh0, bh1);
            }
        }
    }

    if (wrp < 12) {
        const bool wr0 = (lane >> 2) < tval;
        const bool wr1 = (lane >> 2) + 8 < tval;
#pragma unroll
        for (int i = 0; i < 8; i++) {
            const int col = nh * 64 + i * 8 + 2 * (lane & 3);
            float2 o0 = make_float2(c[i].x, c[i].y);
            float2 o1 = make_float2(c[i].z, c[i].w);
            if (tile == 0) {
                float b0 = bias0[col], b1 = bias0[col + 1];
                o0.x += b0; o0.y += b1;
                o1.x += b0; o1.y += b1;
            }
            if (wr0) *(float2*)(O + r0 * 128 + col) = o0;
            if (wr1) *(float2*)(O + (r0 + 8) * 128 + col) = o1;
        }
    }
}

extern "C" __global__ void __launch_bounds__(THREADS, 1)
eqffn_kernel(const float* __restrict__ x,
             const float* __restrict__ nwg,
             const float* __restrict__ b1g,
             const float* __restrict__ gbg,
             const float* __restrict__ b2g,
             const float* __restrict__ tgg,
             const float* __restrict__ fgg,
             float* __restrict__ y,
             int N)
{
    extern __shared__ __align__(16) float sm[];
    float* s_g   = sm + S_G;
    float* s_h1  = sm + S_B1;
    float* s_tg  = sm + S_TG;
    float* s_fg  = sm + S_FG;
    float* s_gb  = sm + S_GB;
    float* s_bb1 = sm + S_BB1;
    float* s_bb2 = sm + S_BB2;
    float* s_nw  = sm + S_NW;
    float* s_red = sm + S_RED;

    const int tid  = threadIdx.x;
    const int lane = tid & 31;
    const int wrp  = tid >> 5;
    const int nodl = wrp >> 1;
    const int half = wrp & 1;

    for (int i = tid; i < 378; i += THREADS) s_tg[i] = tgg[i];
    for (int i = tid; i < 378; i += THREADS) s_fg[i] = fgg[i];
    if (tid < 256) s_gb[tid] = gbg[tid];
    if (tid < 128) { s_bb1[tid] = b1g[tid]; s_bb2[tid] = b2g[tid]; }
    if (tid < 384) s_nw[tid] = nwg[tid];

    const int node = blockIdx.x * NB + nodl;
    const bool valid = node < N;

    // ---------- Phase 0: load x, sumsq, RMS-norm, write PACKED A for GEMM1 ----------
    float v[18];
    float ss = 0.f;
    if (valid) {
        const float* xr = x + (size_t)node * XW + half * 576;
#pragma unroll
        for (int k = 0; k < 18; k++) { v[k] = xr[lane + 32 * k]; ss += v[k] * v[k]; }
    } else {
#pragma unroll
        for (int k = 0; k < 18; k++) v[k] = 0.f;
    }
#pragma unroll
    for (int o = 16; o; o >>= 1) ss += __shfl_xor_sync(0xffffffffu, ss, o);
    if (lane == 0) s_red[wrp] = ss;
    __syncthreads();
    const float sst = s_red[nodl * 2] + s_red[nodl * 2 + 1];
    const float rinv = rsqrtf(sst * (1.0f / 1152.0f) + 1e-6f);

#pragma unroll
    for (int k = 0; k < 18; k++) {
        int j = half * 576 + lane + 32 * k;
        int l, coeff, c;
        if (j < 128)      { l = 0; coeff = 0; c = j; }
        else if (j < 512) { l = 1; int q = j - 128; c = q / 3; coeff = 1 + (q - 3 * c); }
        else              { l = 2; int q = j - 512; c = q / 5; coeff = 4 + (q - 5 * c); }
        ((u32*)s_g)[(coeff * NB + nodl) * 128 + c] = pack_hl(v[k] * rinv * s_nw[l * 128 + c]);
    }
    __syncthreads();

    // ---------- Phase 1: GEMM1 via mma (A already packed) ----------
    gemm_degree_mma((const u32*)s_g, g_w1_pack, s_h1, s_bb1, (u32*)(s_g + 10240));
    __syncthreads();

    // ---------- Phase 2: to_grid -> write PACKED A for GEMM2 ----------
    {
        float4 h1r[MCO];
#pragma unroll
        for (int m = 0; m < MCO; m++)
            h1r[m] = ((const float4*)s_h1)[(m * NB + nodl) * 32 + lane];
        const int a0 = half * 21;
        for (int a = a0; a < a0 + 21; a++) {
            float4 acc = make_float4(0.f, 0.f, 0.f, 0.f);
#pragma unroll
            for (int m = 0; m < MCO; m++) {
                float t = s_tg[a * MCO + m];
                acc.x += t * h1r[m].x; acc.y += t * h1r[m].y;
                acc.z += t * h1r[m].z; acc.w += t * h1r[m].w;
            }
            uint4 pk;
            pk.x = pack_hl(acc.x); pk.y = pack_hl(acc.y);
            pk.z = pack_hl(acc.z); pk.w = pack_hl(acc.w);
            ((uint4*)s_g)[(nodl * AA + a) * 32 + lane] = pk;
        }
    }
    __syncthreads();

    // ---------- Phase 3+4: GEMM2 (336x256x128) via mma + SwiGLU ----------
    {
        u32* sgu  = (u32*)s_g;
        u32* bbuf = (u32*)s_h1;
        const u32 bbuf_addr = smem_u32(bbuf);

        // prologue: issue chunk 0
        for (int p = tid; p < 1024; p += THREADS)
            cp16(bbuf_addr + p * 16, ((const uint4*)g_gw_pack) + p);
        CP_COMMIT();

        const int rt = (wrp < 14) ? (wrp % 7) : 0;
        const int ch = (wrp < 14) ? (wrp / 7) : 0;
        const int rr = rt * 16 + (lane >> 2);
        const int ks = (lane & 3) * 2;

        for (int b = 0; b < 3; b++) {
            const int rbase = b * 112;
            float4 c[16];
#pragma unroll
            for (int i = 0; i < 16; i++) c[i] = make_float4(0.f, 0.f, 0.f, 0.f);

            for (int kc = 0; kc < 8; kc++) {
                CP_WAIT0();
                __syncthreads();
                const int g = b * 8 + kc;
                if (g < 23) {
                    const int nkc = (kc + 1) & 7;
                    const uint4* src = (const uint4*)(g_gw_pack + nkc * 4096);
                    const u32 dstb = bbuf_addr + ((g + 1) & 1) * 16384;
                    for (int p = tid; p < 1024; p += THREADS)
                        cp16(dstb + p * 16, src + p);
                    CP_COMMIT();
                }

                if (wrp < 14) {
                    const u32* Ar = sgu + (rbase + rr) * 128 + kc * 16 + ks;
                    u64 L0 = *(const u64*)(Ar);
                    u64 L1 = *(const u64*)(Ar + 8 * 128);
                    u64 L2 = *(const u64*)(Ar + 8);
                    u64 L3 = *(const u64*)(Ar + 8 * 128 + 8);
                    u32 ah0, ah1, ah2, ah3, al0, al1, al2, al3;
                    { u32 p0 = (u32)L0, p1 = (u32)(L0 >> 32); ah0 = prmt(p0, p1, 0x5410); al0 = prmt(p0, p1, 0x7632); }
                    { u32 p0 = (u32)L1, p1 = (u32)(L1 >> 32); ah1 = prmt(p0, p1, 0x5410); al1 = prmt(p0, p1, 0x7632); }
                    { u32 p0 = (u32)L2, p1 = (u32)(L2 >> 32); ah2 = prmt(p0, p1, 0x5410); al2 = prmt(p0, p1, 0x7632); }
                    { u32 p0 = (u32)L3, p1 = (u32)(L3 >> 32); ah3 = prmt(p0, p1, 0x5410); al3 = prmt(p0, p1, 0x7632); }

                    const u32* bu = bbuf + (g & 1) * 4096;
                    const int jsel2 = 2 * (lane & 3);
#pragma unroll
                    for (int i = 0; i < 16; i++) {
                        const int nt = (i < 8) ? (ch * 8 + i) : (16 + ch * 8 + (i - 8));
                        const int n  = nt * 8 + (lane >> 2);
                        u64 H = *(const u64*)(bu + n * 8 + jsel2);
                        u64 L = *(const u64*)(bu + 2048 + n * 8 + jsel2);
                        u32 bh0 = (u32)H, bh1 = (u32)(H >> 32);
                        u32 bl0 = (u32)L, bl1 = (u32)(L >> 32);
                        mma_bf16(c[i], ah0, ah1, ah2, ah3, bh0, bh1);
                        mma_bf16(c[i], ah0, ah1, ah2, ah3, bl0, bl1);
                        mma_bf16(c[i], al0, al1, al2, al3, bh0, bh1);
                    }
                }
            }
            __syncthreads();   // all MMA reads of this block's A rows done before epilogue writes

            if (wrp < 14) {
                const int r0 = rbase + rr;
#pragma unroll
                for (int i = 0; i < 8; i++) {
                    const int h0 = ch * 64 + i * 8 + (lane & 3) * 2;
                    const float bz0 = s_gb[h0], bz1 = s_gb[h0 + 1];
                    const float bg0 = s_gb[128 + h0], bg1 = s_gb[128 + h0 + 1];
                    float4 z4 = c[i], g4 = c[i + 8];
                    float z0 = z4.x + bz0, z1 = z4.y + bz1;
                    float z2 = z4.z + bz0, z3 = z4.w + bz1;
                    float g0 = g4.x + bg0, g1 = g4.y + bg1;
                    float g2 = g4.z + bg0, g3 = g4.w + bg1;
                    float2 o01, o23;
                    o01.x = z0 * (1.f / (1.f + __expf(-z0))) * g0;
                    o01.y = z1 * (1.f / (1.f + __expf(-z1))) * g1;
                    o23.x = z2 * (1.f / (1.f + __expf(-z2))) * g2;
                    o23.y = z3 * (1.f / (1.f + __expf(-z3))) * g3;
                    *(float2*)(s_g + r0 * 128 + h0) = o01;
                    *(float2*)(s_g + (r0 + 8) * 128 + h0) = o23;
                }
            }
        }
    }
    __syncthreads();

    // ---------- Phase 5: from_grid -> write PACKED A for GEMM3 ----------
    {
        const int m0   = half ? 5 : 0;
        const int mcnt = half ? 4 : 5;
        float4 acc[5];
#pragma unroll
        for (int m = 0; m < 5; m++) acc[m] = make_float4(0.f, 0.f, 0.f, 0.f);
        for (int a = 0; a < AA; a++) {
            float4 g4 = ((const float4*)s_g)[(nodl * AA + a) * 32 + lane];
#pragma unroll
            for (int m = 0; m < 5; m++) {
                if (m < mcnt) {
                    float f = s_fg[(m0 + m) * AA + a];
                    acc[m].x += f * g4.x; acc[m].y += f * g4.y;
                    acc[m].z += f * g4.z; acc[m].w += f * g4.w;
                }
            }
        }
#pragma unroll
        for (int m = 0; m < 5; m++)
            if (m < mcnt) {
                uint4 pk;
                pk.x = pack_hl(acc[m].x); pk.y = pack_hl(acc[m].y);
                pk.z = pack_hl(acc[m].z); pk.w = pack_hl(acc[m].w);
                ((uint4*)s_h1)[((m0 + m) * NB + nodl) * 32 + lane] = pk;
            }
    }
    __syncthreads();

    // ---------- Phase 6: GEMM3 via mma ----------
    gemm_degree_mma((const u32*)s_h1, g_w2_pack, s_g, s_bb2, (u32*)(s_g + 10240));
    __syncthreads();

    // ---------- Phase 7: unpack + store ----------
    if (valid) {
        float* yr = y + (size_t)node * XW;
#pragma unroll
        for (int k = 0; k < 18; k++) {
            int j = half * 576 + lane + 32 * k;
            int coeff, c;
            if (j < 128)      { coeff = 0; c = j; }
            else if (j < 512) { int q = j - 128; c = q / 3; coeff = 1 + (q - 3 * c); }
            else              { int q = j - 512; c = q / 5; coeff = 4 + (q - 5 * c); }
            yr[j] = s_g[(coeff * NB + nodl) * 128 + c];
        }
    }
}

extern "C" void kernel_launch(void* const* d_in, const int* in_sizes, int n_in,
                              void* d_out, int out_size)
{
    const float* x   = (const float*)d_in[0];
    const float* nw  = (const float*)d_in[1];
    const float* w1  = (const float*)d_in[2];
    const float* b1  = (const float*)d_in[3];
    const float* gw  = (const float*)d_in[4];
    const float* gb  = (const float*)d_in[5];
    const float* w2  = (const float*)d_in[6];
    const float* b2  = (const float*)d_in[7];
    const float* tg  = (const float*)d_in[8];
    const float* fg  = (const float*)d_in[9];
    float* y = (float*)d_out;

    const int N = in_sizes[0] / XW;

    prep_kernel<<<128, 512>>>(gw, w1, w2);

    const int smem_bytes = SMEM_FLOATS * 4;
    cudaFuncSetAttribute(eqffn_kernel, cudaFuncAttributeMaxDynamicSharedMemorySize, smem_bytes);
    const int grid = (N + NB - 1) / NB;
    eqffn_kernel<<<grid, THREADS, smem_bytes>>>(x, nw, b1, gb, b2, tg, fg, y, N);
}

// round 16
// speedup vs baseline: 1.0036x; 1.0029x over previous
#include <cuda_runtime.h>
#include <cuda_bf16.h>

typedef unsigned long long u64;
typedef unsigned int u32;

// ---------------- mma.sync bf16 helpers ----------------
__device__ __forceinline__ u32 prmt(u32 a, u32 b, u32 s) {
    u32 d; asm("prmt.b32 %0, %1, %2, %3;" : "=r"(d) : "r"(a), "r"(b), "r"(s));
    return d;
}
__device__ __forceinline__ void mma_bf16(float4& c, u32 a0, u32 a1, u32 a2, u32 a3,
                                         u32 b0, u32 b1) {
    asm("mma.sync.aligned.m16n8k16.row.col.f32.bf16.bf16.f32 "
        "{%0,%1,%2,%3}, {%4,%5,%6,%7}, {%8,%9}, {%0,%1,%2,%3};"
        : "+f"(c.x), "+f"(c.y), "+f"(c.z), "+f"(c.w)
        : "r"(a0), "r"(a1), "r"(a2), "r"(a3), "r"(b0), "r"(b1));
}
// fp32 -> {bf16 hi (low16), bf16 lo (high16)} packed u32
__device__ __forceinline__ u32 pack_hl(float a) {
    __nv_bfloat16 hb = __float2bfloat16_rn(a);
    float r = a - __bfloat162float(hb);
    __nv_bfloat16 lb = __float2bfloat16_rn(r);
    return (u32)__bfloat16_as_ushort(hb) | ((u32)__bfloat16_as_ushort(lb) << 16);
}
__device__ __forceinline__ void split_pair(float2 w, u32& hiw, u32& low) {
    __nv_bfloat16 h0 = __float2bfloat16_rn(w.x);
    __nv_bfloat16 h1 = __float2bfloat16_rn(w.y);
    float r0 = w.x - __bfloat162float(h0);
    float r1 = w.y - __bfloat162float(h1);
    __nv_bfloat16 l0 = __float2bfloat16_rn(r0);
    __nv_bfloat16 l1 = __float2bfloat16_rn(r1);
    hiw = (u32)__bfloat16_as_ushort(h0) | ((u32)__bfloat16_as_ushort(h1) << 16);
    low = (u32)__bfloat16_as_ushort(l0) | ((u32)__bfloat16_as_ushort(l1) << 16);
}
__device__ __forceinline__ u32 smem_u32(const void* p) {
    u32 a; asm("{ .reg .u64 t; cvta.to.shared.u64 t, %1; cvt.u32.u64 %0, t; }" : "=r"(a) : "l"(p));
    return a;
}
__device__ __forceinline__ void cp16(u32 dst, const void* src) {
    asm volatile("cp.async.cg.shared.global [%0], [%1], 16;" :: "r"(dst), "l"(src));
}
#define CP_COMMIT() asm volatile("cp.async.commit_group;" ::: "memory")
#define CP_WAIT0()  asm volatile("cp.async.wait_group 0;" ::: "memory")

// ---------------- problem constants ----------------
#define NB   8
#define MCO  9
#define AA   42
#define XW   1152
#define THREADS 512

// ---------------- prepacked weights (filled by prep_kernel) ----------------
__device__ u32 g_gw_pack[8 * 4096];   // grid_w: [8 kc][hi:2048 | lo:2048]
__device__ u32 g_w1_pack[8 * 6144];   // w1: [8 kc][hi:3072 | lo:3072], n=deg*128+h
__device__ u32 g_w2_pack[8 * 6144];

// ---------------- shared memory layout (floats) ----------------
#define S_G    0                    // 336*128 (g/gg/out; rows 80+ alias W staging for GEMM1/3)
#define S_B1   43008                // 72*128 (h1/h2); GEMM2 B staging aliases (8192 u32)
#define S_TG   56320
#define S_FG   (S_TG + 378)
#define S_GB   (S_FG + 378)
#define S_BB1  (S_GB + 256)
#define S_BB2  (S_BB1 + 128)
#define S_NW   (S_BB2 + 128)
#define S_RED  (S_NW + 384)
#define SMEM_FLOATS (S_RED + 16)

// ---------------- prep kernel: convert weights once ----------------
extern "C" __global__ void prep_kernel(const float* __restrict__ gw,
                                       const float* __restrict__ w1,
                                       const float* __restrict__ w2)
{
    const int t = blockIdx.x * blockDim.x + threadIdx.x;
    const int stride = gridDim.x * blockDim.x;
    for (int p = t; p < 16384; p += stride) {
        int n = p >> 6, kc = (p >> 3) & 7, j = p & 7;
        float2 w = *(const float2*)(gw + n * 128 + kc * 16 + 2 * j);
        u32 hiw, low; split_pair(w, hiw, low);
        int pos = 2 * (j & 3) + (j >> 2);
        g_gw_pack[kc * 4096 + n * 8 + pos] = hiw;
        g_gw_pack[kc * 4096 + 2048 + n * 8 + pos] = low;
    }
    for (int p = t; p < 24576; p += stride) {
        int n = p >> 6, kc = (p >> 3) & 7, j = p & 7;
        int pos = 2 * (j & 3) + (j >> 2);
        {
            float2 w = *(const float2*)(w1 + n * 128 + kc * 16 + 2 * j);
            u32 hiw, low; split_pair(w, hiw, low);
            g_w1_pack[kc * 6144 + n * 8 + pos] = hiw;
            g_w1_pack[kc * 6144 + 3072 + n * 8 + pos] = low;
        }
        {
            float2 w = *(const float2*)(w2 + n * 128 + kc * 16 + 2 * j);
            u32 hiw, low; split_pair(w, hiw, low);
            g_w2_pack[kc * 6144 + n * 8 + pos] = hiw;
            g_w2_pack[kc * 6144 + 3072 + n * 8 + pos] = low;
        }
    }
}

// ---------------- GEMM1/GEMM3: per-degree 72x128x128 via mma.sync ----------------
// Apk: packed A (72 rows x 128 u32). wpk: prepacked weights. O: fp32 72x128.
// wbuf: smem staging 2*6144 u32 (cp.async double-buffered).
__device__ __forceinline__ void gemm_degree_mma(const u32* __restrict__ Apk,
                                                const u32* __restrict__ wpk,
                                                float* __restrict__ O,
                                                const float* __restrict__ bias0,
                                                u32* __restrict__ wbuf)
{
    const int tid  = threadIdx.x;
    const int lane = tid & 31;
    const int wrp  = tid >> 5;
    const u32 wbuf_addr = smem_u32(wbuf);

    // prologue: issue chunk 0 into buffer 0
    for (int p = tid; p < 1536; p += THREADS)
        cp16(wbuf_addr + p * 16, ((const uint4*)wpk) + p);
    CP_COMMIT();

    const int tile = (wrp < 12) ? (wrp >> 1) : 0;
    const int nh   = wrp & 1;
    int trow, tval, tdeg;
    if (tile == 0)      { trow = 0;                 tval = 8;                  tdeg = 0; }
    else if (tile <= 2) { trow = 8 + 16 * (tile - 1);  tval = (tile == 1) ? 16 : 8;  tdeg = 1; }
    else                { trow = 32 + 16 * (tile - 3); tval = (tile == 5) ? 8 : 16;  tdeg = 2; }

    float4 c[8];
#pragma unroll
    for (int i = 0; i < 8; i++) c[i] = make_float4(0.f, 0.f, 0.f, 0.f);

    const int r0 = trow + (lane >> 2);
    const u32* Ar = Apk + r0 * 128 + (lane & 3) * 2;
    const int bbase = (tdeg * 128 + nh * 64) * 8 + 2 * (lane & 3);

    for (int kc = 0; kc < 8; kc++) {
        CP_WAIT0();
        __syncthreads();
        if (kc < 7) {
            const uint4* src = (const uint4*)(wpk + (kc + 1) * 6144);
            const u32 dstb = wbuf_addr + ((kc + 1) & 1) * 24576;
            for (int p = tid; p < 1536; p += THREADS)
                cp16(dstb + p * 16, src + p);
            CP_COMMIT();
        }
        if (wrp < 12) {
            const u32* a = Ar + kc * 16;
            u64 L0 = *(const u64*)(a);
            u64 L1 = *(const u64*)(a + 8 * 128);
            u64 L2 = *(const u64*)(a + 8);
            u64 L3 = *(const u64*)(a + 8 * 128 + 8);
            u32 ah0, ah1, ah2, ah3, al0, al1, al2, al3;
            { u32 p0 = (u32)L0, p1 = (u32)(L0 >> 32); ah0 = prmt(p0, p1, 0x5410); al0 = prmt(p0, p1, 0x7632); }
            { u32 p0 = (u32)L1, p1 = (u32)(L1 >> 32); ah1 = prmt(p0, p1, 0x5410); al1 = prmt(p0, p1, 0x7632); }
            { u32 p0 = (u32)L2, p1 = (u32)(L2 >> 32); ah2 = prmt(p0, p1, 0x5410); al2 = prmt(p0, p1, 0x7632); }
            { u32 p0 = (u32)L3, p1 = (u32)(L3 >> 32); ah3 = prmt(p0, p1, 0x5410); al3 = prmt(p0, p1, 0x7632); }

            const u32* bu = wbuf + (kc & 1) * 6144 + bbase;
#pragma unroll
            for (int i = 0; i < 8; i++) {
                const int noff = (i * 8 + (lane >> 2)) * 8;
                u64 H = *(const u64*)(bu + noff);
                u64 L = *(const u64*)(bu + 3072 + noff);
                u32 bh0 = (u32)H, bh1 = (u32)(H >> 32);
                u32 bl0 = (u32)L, bl1 = (u32)(L >> 32);
                mma_bf16(c[i], ah0, ah1, ah2, ah3, bh0, bh1);
                mma_bf16(c[i], ah0, ah1, ah2, ah3, bl0, bl1);
                mma_bf16(c[i], al0, al1, al2, al3, bh0, bh1);
            }
        }
    }

    if (wrp < 12) {
        const bool wr0 = (lane >> 2) < tval;
        const bool wr1 = (lane >> 2) + 8 < tval;
#pragma unroll
        for (int i = 0; i < 8; i++) {
            const int col = nh * 64 + i * 8 + 2 * (lane & 3);
            float2 o0 = make_float2(c[i].x, c[i].y);
            float2 o1 = make_float2(c[i].z, c[i].w);
            if (tile == 0) {
                float b0 = bias0[col], b1 = bias0[col + 1];
                o0.x += b0; o0.y += b1;
                o1.x += b0; o1.y += b1;
            }
            if (wr0) *(float2*)(O + r0 * 128 + col) = o0;
            if (wr1) *(float2*)(O + (r0 + 8) * 128 + col) = o1;
        }
    }
}

extern "C" __global__ void __launch_bounds__(THREADS, 1)
eqffn_kernel(const float* __restrict__ x,
             const float* __restrict__ nwg,
             const float* __restrict__ b1g,
             const float* __restrict__ gbg,
             const float* __restrict__ b2g,
             const float* __restrict__ tgg,
             const float* __restrict__ fgg,
             float* __restrict__ y,
             int N)
{
    extern __shared__ __align__(16) float sm[];
    float* s_g   = sm + S_G;
    float* s_h1  = sm + S_B1;
    float* s_tg  = sm + S_TG;
    float* s_fg  = sm + S_FG;
    float* s_gb  = sm + S_GB;
    float* s_bb1 = sm + S_BB1;
    float* s_bb2 = sm + S_BB2;
    float* s_nw  = sm + S_NW;
    float* s_red = sm + S_RED;

    const int tid  = threadIdx.x;
    const int lane = tid & 31;
    const int wrp  = tid >> 5;
    const int nodl = wrp >> 1;
    const int half = wrp & 1;

    for (int i = tid; i < 378; i += THREADS) s_tg[i] = tgg[i];
    for (int i = tid; i < 378; i += THREADS) s_fg[i] = fgg[i];
    if (tid < 256) s_gb[tid] = gbg[tid];
    if (tid < 128) { s_bb1[tid] = b1g[tid]; s_bb2[tid] = b2g[tid]; }
    if (tid < 384) s_nw[tid] = nwg[tid];

    const int node = blockIdx.x * NB + nodl;
    const bool valid = node < N;

    // ---------- Phase 0: load x, sumsq, RMS-norm, write PACKED A for GEMM1 ----------
    float v[18];
    float ss = 0.f;
    if (valid) {
        const float* xr = x + (size_t)node * XW + half * 576;
#pragma unroll
        for (int k = 0; k < 18; k++) { v[k] = xr[lane + 32 * k]; ss += v[k] * v[k]; }
    } else {
#pragma unroll
        for (int k = 0; k < 18; k++) v[k] = 0.f;
    }
#pragma unroll
    for (int o = 16; o; o >>= 1) ss += __shfl_xor_sync(0xffffffffu, ss, o);
    if (lane == 0) s_red[wrp] = ss;
    __syncthreads();
    const float sst = s_red[nodl * 2] + s_red[nodl * 2 + 1];
    const float rinv = rsqrtf(sst * (1.0f / 1152.0f) + 1e-6f);

#pragma unroll
    for (int k = 0; k < 18; k++) {
        int j = half * 576 + lane + 32 * k;
        int l, coeff, c;
        if (j < 128)      { l = 0; coeff = 0; c = j; }
        else if (j < 512) { l = 1; int q = j - 128; c = q / 3; coeff = 1 + (q - 3 * c); }
        else              { l = 2; int q = j - 512; c = q / 5; coeff = 4 + (q - 5 * c); }
        ((u32*)s_g)[(coeff * NB + nodl) * 128 + c] = pack_hl(v[k] * rinv * s_nw[l * 128 + c]);
    }
    __syncthreads();

    // ---------- Phase 1: GEMM1 via mma (A already packed) ----------
    gemm_degree_mma((const u32*)s_g, g_w1_pack, s_h1, s_bb1, (u32*)(s_g + 10240));
    __syncthreads();

    // ---------- Phase 2: to_grid -> write PACKED A for GEMM2 ----------
    {
        float4 h1r[MCO];
#pragma unroll
        for (int m = 0; m < MCO; m++)
            h1r[m] = ((const float4*)s_h1)[(m * NB + nodl) * 32 + lane];
        const int a0 = half * 21;
        for (int a = a0; a < a0 + 21; a++) {
            float4 acc = make_float4(0.f, 0.f, 0.f, 0.f);
#pragma unroll
            for (int m = 0; m < MCO; m++) {
                float t = s_tg[a * MCO + m];
                acc.x += t * h1r[m].x; acc.y += t * h1r[m].y;
                acc.z += t * h1r[m].z; acc.w += t * h1r[m].w;
            }
            uint4 pk;
            pk.x = pack_hl(acc.x); pk.y = pack_hl(acc.y);
            pk.z = pack_hl(acc.z); pk.w = pack_hl(acc.w);
            ((uint4*)s_g)[(nodl * AA + a) * 32 + lane] = pk;
        }
    }
    __syncthreads();

    // ---------- Phase 3+4: GEMM2 (336x256x128) via mma + SwiGLU ----------
    {
        u32* sgu  = (u32*)s_g;
        u32* bbuf = (u32*)s_h1;
        const u32 bbuf_addr = smem_u32(bbuf);

        // prologue: issue chunk 0
        for (int p = tid; p < 1024; p += THREADS)
            cp16(bbuf_addr + p * 16, ((const uint4*)g_gw_pack) + p);
        CP_COMMIT();

        const int rt = (wrp < 14) ? (wrp % 7) : 0;
        const int ch = (wrp < 14) ? (wrp / 7) : 0;
        const int rr = rt * 16 + (lane >> 2);
        const int ks = (lane & 3) * 2;

        for (int b = 0; b < 3; b++) {
            const int rbase = b * 112;
            float4 c[16];
#pragma unroll
            for (int i = 0; i < 16; i++) c[i] = make_float4(0.f, 0.f, 0.f, 0.f);

            for (int kc = 0; kc < 8; kc++) {
                CP_WAIT0();
                __syncthreads();
                const int g = b * 8 + kc;
                if (g < 23) {
                    const int nkc = (kc + 1) & 7;
                    const uint4* src = (const uint4*)(g_gw_pack + nkc * 4096);
                    const u32 dstb = bbuf_addr + ((g + 1) & 1) * 16384;
                    for (int p = tid; p < 1024; p += THREADS)
                        cp16(dstb + p * 16, src + p);
                    CP_COMMIT();
                }

                if (wrp < 14) {
                    const u32* Ar = sgu + (rbase + rr) * 128 + kc * 16 + ks;
                    u64 L0 = *(const u64*)(Ar);
                    u64 L1 = *(const u64*)(Ar + 8 * 128);
                    u64 L2 = *(const u64*)(Ar + 8);
                    u64 L3 = *(const u64*)(Ar + 8 * 128 + 8);
                    u32 ah0, ah1, ah2, ah3, al0, al1, al2, al3;
                    { u32 p0 = (u32)L0, p1 = (u32)(L0 >> 32); ah0 = prmt(p0, p1, 0x5410); al0 = prmt(p0, p1, 0x7632); }
                    { u32 p0 = (u32)L1, p1 = (u32)(L1 >> 32); ah1 = prmt(p0, p1, 0x5410); al1 = prmt(p0, p1, 0x7632); }
                    { u32 p0 = (u32)L2, p1 = (u32)(L2 >> 32); ah2 = prmt(p0, p1, 0x5410); al2 = prmt(p0, p1, 0x7632); }
                    { u32 p0 = (u32)L3, p1 = (u32)(L3 >> 32); ah3 = prmt(p0, p1, 0x5410); al3 = prmt(p0, p1, 0x7632); }

                    const u32* bu = bbuf + (g & 1) * 4096;
                    const int jsel2 = 2 * (lane & 3);
#pragma unroll
                    for (int i = 0; i < 16; i++) {
                        const int nt = (i < 8) ? (ch * 8 + i) : (16 + ch * 8 + (i - 8));
                        const int n  = nt * 8 + (lane >> 2);
                        u64 H = *(const u64*)(bu + n * 8 + jsel2);
                        u64 L = *(const u64*)(bu + 2048 + n * 8 + jsel2);
                        u32 bh0 = (u32)H, bh1 = (u32)(H >> 32);
                        u32 bl0 = (u32)L, bl1 = (u32)(L >> 32);
                        mma_bf16(c[i], ah0, ah1, ah2, ah3, bh0, bh1);
                        mma_bf16(c[i], ah0, ah1, ah2, ah3, bl0, bl1);
                        mma_bf16(c[i], al0, al1, al2, al3, bh0, bh1);
                    }
                }
            }
            __syncthreads();   // all MMA reads of this block's A rows done before epilogue writes

            if (wrp < 14) {
                const int r0 = rbase + rr;
#pragma unroll
                for (int i = 0; i < 8; i++) {
                    const int h0 = ch * 64 + i * 8 + (lane & 3) * 2;
                    const float bz0 = s_gb[h0], bz1 = s_gb[h0 + 1];
                    const float bg0 = s_gb[128 + h0], bg1 = s_gb[128 + h0 + 1];
                    float4 z4 = c[i], g4 = c[i + 8];
                    float z0 = z4.x + bz0, z1 = z4.y + bz1;
                    float z2 = z4.z + bz0, z3 = z4.w + bz1;
                    float g0 = g4.x + bg0, g1 = g4.y + bg1;
                    float g2 = g4.z + bg0, g3 = g4.w + bg1;
                    float2 o01, o23;
                    o01.x = z0 * (1.f / (1.f + __expf(-z0))) * g0;
                    o01.y = z1 * (1.f / (1.f + __expf(-z1))) * g1;
                    o23.x = z2 * (1.f / (1.f + __expf(-z2))) * g2;
                    o23.y = z3 * (1.f / (1.f + __expf(-z3))) * g3;
                    *(float2*)(s_g + r0 * 128 + h0) = o01;
                    *(float2*)(s_g + (r0 + 8) * 128 + h0) = o23;
                }
            }
        }
    }
    __syncthreads();

    // ---------- Phase 5: from_grid -> write PACKED A for GEMM3 ----------
    {
        const int m0   = half ? 5 : 0;
        const int mcnt = half ? 4 : 5;
        float4 acc[5];
#pragma unroll
        for (int m = 0; m < 5; m++) acc[m] = make_float4(0.f, 0.f, 0.f, 0.f);
        for (int a = 0; a < AA; a++) {
            float4 g4 = ((const float4*)s_g)[(nodl * AA + a) * 32 + lane];
#pragma unroll
            for (int m = 0; m < 5; m++) {
                if (m < mcnt) {
                    float f = s_fg[(m0 + m) * AA + a];
                    acc[m].x += f * g4.x; acc[m].y += f * g4.y;
                    acc[m].z += f * g4.z; acc[m].w += f * g4.w;
                }
            }
        }
#pragma unroll
        for (int m = 0; m < 5; m++)
            if (m < mcnt) {
                uint4 pk;
                pk.x = pack_hl(acc[m].x); pk.y = pack_hl(acc[m].y);
                pk.z = pack_hl(acc[m].z); pk.w = pack_hl(acc[m].w);
                ((uint4*)s_h1)[((m0 + m) * NB + nodl) * 32 + lane] = pk;
            }
    }
    __syncthreads();

    // ---------- Phase 6: GEMM3 via mma ----------
    gemm_degree_mma((const u32*)s_h1, g_w2_pack, s_g, s_bb2, (u32*)(s_g + 10240));
    __syncthreads();

    // ---------- Phase 7: unpack + store ----------
    if (valid) {
        float* yr = y + (size_t)node * XW;
#pragma unroll
        for (int k = 0; k < 18; k++) {
            int j = half * 576 + lane + 32 * k;
            int coeff, c;
            if (j < 128)      { coeff = 0; c = j; }
            else if (j < 512) { int q = j - 128; c = q / 3; coeff = 1 + (q - 3 * c); }
            else              { int q = j - 512; c = q / 5; coeff = 4 + (q - 5 * c); }
            yr[j] = s_g[(coeff * NB + nodl) * 128 + c];
        }
    }
}

extern "C" void kernel_launch(void* const* d_in, const int* in_sizes, int n_in,
                              void* d_out, int out_size)
{
    const float* x   = (const float*)d_in[0];
    const float* nw  = (const float*)d_in[1];
    const float* w1  = (const float*)d_in[2];
    const float* b1  = (const float*)d_in[3];
    const float* gw  = (const float*)d_in[4];
    const float* gb  = (const float*)d_in[5];
    const float* w2  = (const float*)d_in[6];
    const float* b2  = (const float*)d_in[7];
    const float* tg  = (const float*)d_in[8];
    const float* fg  = (const float*)d_in[9];
    float* y = (float*)d_out;

    const int N = in_sizes[0] / XW;

    prep_kernel<<<128, 512>>>(gw, w1, w2);

    const int smem_bytes = SMEM_FLOATS * 4;
    cudaFuncSetAttribute(eqffn_kernel, cudaFuncAttributeMaxDynamicSharedMemorySize, smem_bytes);
    const int grid = (N + NB - 1) / NB;
    eqffn_kernel<<<grid, THREADS, smem_bytes>>>(x, nw, b1, gb, b2, tg, fg, y, N);
}